// round 2
// baseline (speedup 1.0000x reference)
#include <cuda_runtime.h>
#include <cuda_bf16.h>
#include <math.h>

// Problem constants (fixed shapes)
#define B_DIM 8192
#define D_DIM 512
#define H_DIM 4
#define M_DIM 128
#define W_DIM 64
#define N_DIM (H_DIM * W_DIM)   // 256
#define EPS 1e-6f

// Scratch for tanh(hidden @ W_key + b_key): [B, 256] fp32 = 8 MB
__device__ float g_key[(size_t)B_DIM * N_DIM];

// ---------------------------------------------------------------------------
// Kernel A: tiled fp32 GEMM  key = tanh(hidden[B,512] @ W_key[512,256] + b_key)
// BM=64, BN=128, BK=16, 256 threads, 4x8 register tile per thread.
// ---------------------------------------------------------------------------
#define BM 64
#define BN 128
#define BK 16
#define TM 4
#define TN 8

__global__ __launch_bounds__(256, 2)
void key_gemm_kernel(const float* __restrict__ A,      // hidden [B, 512]
                     const float* __restrict__ Wk,     // [512, 256]
                     const float* __restrict__ bk,     // [256]
                     float* __restrict__ out)          // g_key [B, 256]
{
    __shared__ float As[BK][BM + 4];
    __shared__ float Bs[BK][BN];

    const int tid = threadIdx.x;
    const int tx = tid & 15;        // 0..15  -> cols (TN=8 each)
    const int ty = tid >> 4;        // 0..15  -> rows (TM=4 each)

    const int row0 = blockIdx.y * BM;
    const int col0 = blockIdx.x * BN;

    // A tile load mapping: 64x16 floats = 256 float4 -> 1 per thread
    const int arow = tid >> 2;          // 0..63
    const int acol = (tid & 3) * 4;     // 0,4,8,12

    float acc[TM][TN] = {};

    for (int k0 = 0; k0 < D_DIM; k0 += BK) {
        // load A tile (transposed into As[k][m])
        float4 av = *(const float4*)&A[(size_t)(row0 + arow) * D_DIM + k0 + acol];
        As[acol + 0][arow] = av.x;
        As[acol + 1][arow] = av.y;
        As[acol + 2][arow] = av.z;
        As[acol + 3][arow] = av.w;

        // load B tile: 16x128 floats = 512 float4 -> 2 per thread
        #pragma unroll
        for (int j = 0; j < 2; j++) {
            int idx = tid + j * 256;
            int br  = idx >> 5;          // 0..15
            int bc  = (idx & 31) * 4;    // 0..124
            *(float4*)&Bs[br][bc] =
                *(const float4*)&Wk[(size_t)(k0 + br) * N_DIM + col0 + bc];
        }
        __syncthreads();

        #pragma unroll
        for (int k = 0; k < BK; k++) {
            float a[TM], b[TN];
            #pragma unroll
            for (int i = 0; i < TM; i++) a[i] = As[k][ty * TM + i];
            #pragma unroll
            for (int j = 0; j < TN; j += 4) {
                float4 bv = *(const float4*)&Bs[k][tx * TN + j];
                b[j + 0] = bv.x; b[j + 1] = bv.y; b[j + 2] = bv.z; b[j + 3] = bv.w;
            }
            #pragma unroll
            for (int i = 0; i < TM; i++)
                #pragma unroll
                for (int j = 0; j < TN; j++)
                    acc[i][j] += a[i] * b[j];
        }
        __syncthreads();
    }

    // epilogue: tanh(acc + bias), vectorized store
    float bia[TN];
    #pragma unroll
    for (int j = 0; j < TN; j++) bia[j] = bk[col0 + tx * TN + j];

    #pragma unroll
    for (int i = 0; i < TM; i++) {
        int r = row0 + ty * TM + i;
        float4 o0, o1;
        o0.x = tanhf(acc[i][0] + bia[0]);
        o0.y = tanhf(acc[i][1] + bia[1]);
        o0.z = tanhf(acc[i][2] + bia[2]);
        o0.w = tanhf(acc[i][3] + bia[3]);
        o1.x = tanhf(acc[i][4] + bia[4]);
        o1.y = tanhf(acc[i][5] + bia[5]);
        o1.z = tanhf(acc[i][6] + bia[6]);
        o1.w = tanhf(acc[i][7] + bia[7]);
        float* op = &out[(size_t)r * N_DIM + col0 + tx * TN];
        *(float4*)op       = o0;
        *(float4*)(op + 4) = o1;
    }
}

// ---------------------------------------------------------------------------
// Kernel B: per-batch-row attention. 1 block (128 threads) per b.
//  - warp h computes u2[h] and beta[h]
//  - thread m streams memory[b,m,:], computes v2 + 4 head dots
//  - block softmax over m per head
// ---------------------------------------------------------------------------
__global__ __launch_bounds__(M_DIM)
void attn_kernel(const float* __restrict__ hidden,   // [B, 512]
                 const float* __restrict__ memory,   // [B, 128, 64]
                 const float* __restrict__ Wb,       // [512, 4]
                 const float* __restrict__ bb,       // [4]
                 const float* __restrict__ key,      // g_key [B, 256]
                 float* __restrict__ out)            // [B, 4, 128]
{
    __shared__ float key_s[N_DIM];
    __shared__ float u2_s[H_DIM];
    __shared__ float beta_s[H_DIM];
    __shared__ float red_max[H_DIM][4];
    __shared__ float red_sum[H_DIM][4];

    const int b    = blockIdx.x;
    const int tid  = threadIdx.x;
    const int lane = tid & 31;
    const int warp = tid >> 5;   // 0..3 == head id

    // load key row into smem (256 floats, float2 each)
    {
        const float2* kp = (const float2*)&key[(size_t)b * N_DIM];
        *((float2*)key_s + tid) = kp[tid];
    }
    __syncthreads();

    // warp h: u2[h] = sum(key[h]^2) + EPS
    {
        float t0 = key_s[warp * W_DIM + lane];
        float t1 = key_s[warp * W_DIM + 32 + lane];
        float ss = t0 * t0 + t1 * t1;
        #pragma unroll
        for (int off = 16; off > 0; off >>= 1)
            ss += __shfl_xor_sync(0xffffffffu, ss, off);
        if (lane == 0) u2_s[warp] = ss + EPS;
    }

    // warp h: beta[h] = softplus(hidden[b] . Wb[:,h] + bb[h])
    {
        const float* hrow = &hidden[(size_t)b * D_DIM];
        float s = 0.f;
        #pragma unroll 4
        for (int d = lane; d < D_DIM; d += 32)
            s += hrow[d] * Wb[d * H_DIM + warp];
        #pragma unroll
        for (int off = 16; off > 0; off >>= 1)
            s += __shfl_xor_sync(0xffffffffu, s, off);
        if (lane == 0) {
            float x = s + bb[warp];
            beta_s[warp] = (x > 15.f) ? x : log1pf(expf(x));
        }
    }
    __syncthreads();

    // thread m: stream memory row, accumulate v2 and 4 head dots
    const int m = tid;
    const float4* mp = (const float4*)&memory[((size_t)b * M_DIM + m) * W_DIM];

    float v2 = 0.f;
    float num[H_DIM] = {0.f, 0.f, 0.f, 0.f};

    #pragma unroll
    for (int i = 0; i < W_DIM / 4; i++) {
        float4 v = mp[i];
        v2 += v.x * v.x + v.y * v.y + v.z * v.z + v.w * v.w;
        #pragma unroll
        for (int h = 0; h < H_DIM; h++) {
            const float* ks = &key_s[h * W_DIM + i * 4];
            num[h] += ks[0] * v.x + ks[1] * v.y + ks[2] * v.z + ks[3] * v.w;
        }
    }
    v2 += EPS;

    // logits
    float l[H_DIM];
    #pragma unroll
    for (int h = 0; h < H_DIM; h++) {
        float den = sqrtf(u2_s[h] * v2);
        float k   = num[h] / (den + EPS);
        l[h] = k * beta_s[h];
    }

    // block softmax over the 128 threads, per head
    float mx[H_DIM];
    #pragma unroll
    for (int h = 0; h < H_DIM; h++) {
        float t = l[h];
        #pragma unroll
        for (int off = 16; off > 0; off >>= 1)
            t = fmaxf(t, __shfl_xor_sync(0xffffffffu, t, off));
        if (lane == 0) red_max[h][warp] = t;
    }
    __syncthreads();
    #pragma unroll
    for (int h = 0; h < H_DIM; h++)
        mx[h] = fmaxf(fmaxf(red_max[h][0], red_max[h][1]),
                      fmaxf(red_max[h][2], red_max[h][3]));

    float e[H_DIM], sm[H_DIM];
    #pragma unroll
    for (int h = 0; h < H_DIM; h++) {
        e[h] = __expf(l[h] - mx[h]);
        float t = e[h];
        #pragma unroll
        for (int off = 16; off > 0; off >>= 1)
            t += __shfl_xor_sync(0xffffffffu, t, off);
        if (lane == 0) red_sum[h][warp] = t;
    }
    __syncthreads();
    #pragma unroll
    for (int h = 0; h < H_DIM; h++)
        sm[h] = red_sum[h][0] + red_sum[h][1] + red_sum[h][2] + red_sum[h][3];

    // write wc[b,h,m]
    #pragma unroll
    for (int h = 0; h < H_DIM; h++)
        out[((size_t)b * H_DIM + h) * M_DIM + m] = e[h] / sm[h];
}

// ---------------------------------------------------------------------------
// Launch
// ---------------------------------------------------------------------------
extern "C" void kernel_launch(void* const* d_in, const int* in_sizes, int n_in,
                              void* d_out, int out_size)
{
    const float* hidden = (const float*)d_in[0];   // [8192, 512]
    const float* memory = (const float*)d_in[1];   // [8192, 128, 64]
    const float* W_key  = (const float*)d_in[2];   // [512, 256]
    const float* b_key  = (const float*)d_in[3];   // [256]
    const float* W_beta = (const float*)d_in[4];   // [512, 4]
    const float* b_beta = (const float*)d_in[5];   // [4]
    float* out = (float*)d_out;                    // [8192, 4, 128]

    float* keybuf;
    cudaGetSymbolAddress((void**)&keybuf, g_key);

    dim3 gridA(N_DIM / BN, B_DIM / BM);   // (2, 128)
    key_gemm_kernel<<<gridA, 256>>>(hidden, W_key, b_key, keybuf);

    attn_kernel<<<B_DIM, M_DIM>>>(hidden, memory, W_beta, b_beta, keybuf, out);
}

// round 3
// speedup vs baseline: 2.0295x; 2.0295x over previous
#include <cuda_runtime.h>
#include <cuda_bf16.h>
#include <math.h>

// Problem constants (fixed shapes)
#define B_DIM 8192
#define D_DIM 512
#define H_DIM 4
#define M_DIM 128
#define W_DIM 64
#define N_DIM (H_DIM * W_DIM)   // 256
#define EPS 1e-6f

// Scratch for tanh(hidden @ W_key + b_key): [B, 256] fp32 = 8 MB
__device__ float g_key[(size_t)B_DIM * N_DIM];

// ---------------------------------------------------------------------------
// Kernel A: tiled fp32 GEMM  key = tanh(hidden[B,512] @ W_key[512,256] + b_key)
// BM=128, BN=128, BK=16, 256 threads, 8x8 register tile, double-buffered smem.
// Grid = (256/128, 8192/128) = (2, 64) = 128 blocks -> exactly 1 wave.
// ---------------------------------------------------------------------------
#define GBM 128
#define GBN 128
#define GBK 16

__global__ __launch_bounds__(256)
void key_gemm_kernel(const float* __restrict__ A,      // hidden [B, 512]
                     const float* __restrict__ Wk,     // [512, 256]
                     const float* __restrict__ bk,     // [256]
                     float* __restrict__ out)          // g_key [B, 256]
{
    __shared__ float As[2][GBK][GBM + 4];
    __shared__ float Bs[2][GBK][GBN];

    const int tid = threadIdx.x;
    const int tx = tid & 15;        // 0..15 -> cols (8 each)
    const int ty = tid >> 4;        // 0..15 -> rows (8 each)

    const int row0 = blockIdx.y * GBM;
    const int col0 = blockIdx.x * GBN;

    // Per-thread load mapping (2 float4 for A, 2 float4 for B per tile)
    // A tile: 128x16 floats = 512 float4 ; f -> arow=f>>2, acol=(f&3)*4
    // B tile: 16x128 floats = 512 float4 ; f -> brow=f>>5, bcol=(f&31)*4
    const int f0 = tid, f1 = tid + 256;
    const int ar0 = f0 >> 2, ac0 = (f0 & 3) << 2;
    const int ar1 = f1 >> 2, ac1 = (f1 & 3) << 2;
    const int br0 = f0 >> 5, bc0 = (f0 & 31) << 2;
    const int br1 = f1 >> 5, bc1 = (f1 & 31) << 2;

    float acc[8][8] = {};

    // ---- prologue: load tile k0=0 into buffer 0 ----
    {
        float4 a0 = *(const float4*)&A[(size_t)(row0 + ar0) * D_DIM + ac0];
        float4 a1 = *(const float4*)&A[(size_t)(row0 + ar1) * D_DIM + ac1];
        float4 b0 = *(const float4*)&Wk[(size_t)br0 * N_DIM + col0 + bc0];
        float4 b1 = *(const float4*)&Wk[(size_t)br1 * N_DIM + col0 + bc1];
        As[0][ac0 + 0][ar0] = a0.x; As[0][ac0 + 1][ar0] = a0.y;
        As[0][ac0 + 2][ar0] = a0.z; As[0][ac0 + 3][ar0] = a0.w;
        As[0][ac1 + 0][ar1] = a1.x; As[0][ac1 + 1][ar1] = a1.y;
        As[0][ac1 + 2][ar1] = a1.z; As[0][ac1 + 3][ar1] = a1.w;
        *(float4*)&Bs[0][br0][bc0] = b0;
        *(float4*)&Bs[0][br1][bc1] = b1;
    }
    __syncthreads();

    const int NSTEP = D_DIM / GBK;   // 32
    #pragma unroll 1
    for (int s = 0; s < NSTEP; s++) {
        const int cbuf = s & 1;
        const int nbuf = cbuf ^ 1;
        const int k0n  = (s + 1) * GBK;

        float4 pa0, pa1, pb0, pb1;
        if (s + 1 < NSTEP) {
            pa0 = *(const float4*)&A[(size_t)(row0 + ar0) * D_DIM + k0n + ac0];
            pa1 = *(const float4*)&A[(size_t)(row0 + ar1) * D_DIM + k0n + ac1];
            pb0 = *(const float4*)&Wk[(size_t)(k0n + br0) * N_DIM + col0 + bc0];
            pb1 = *(const float4*)&Wk[(size_t)(k0n + br1) * N_DIM + col0 + bc1];
        }

        #pragma unroll
        for (int k = 0; k < GBK; k++) {
            float a[8], b[8];
            #pragma unroll
            for (int i = 0; i < 8; i += 4) {
                float4 av = *(const float4*)&As[cbuf][k][ty * 8 + i];
                a[i + 0] = av.x; a[i + 1] = av.y; a[i + 2] = av.z; a[i + 3] = av.w;
            }
            #pragma unroll
            for (int j = 0; j < 8; j += 4) {
                float4 bv = *(const float4*)&Bs[cbuf][k][tx * 8 + j];
                b[j + 0] = bv.x; b[j + 1] = bv.y; b[j + 2] = bv.z; b[j + 3] = bv.w;
            }
            #pragma unroll
            for (int i = 0; i < 8; i++)
                #pragma unroll
                for (int j = 0; j < 8; j++)
                    acc[i][j] += a[i] * b[j];
        }

        if (s + 1 < NSTEP) {
            As[nbuf][ac0 + 0][ar0] = pa0.x; As[nbuf][ac0 + 1][ar0] = pa0.y;
            As[nbuf][ac0 + 2][ar0] = pa0.z; As[nbuf][ac0 + 3][ar0] = pa0.w;
            As[nbuf][ac1 + 0][ar1] = pa1.x; As[nbuf][ac1 + 1][ar1] = pa1.y;
            As[nbuf][ac1 + 2][ar1] = pa1.z; As[nbuf][ac1 + 3][ar1] = pa1.w;
            *(float4*)&Bs[nbuf][br0][bc0] = pb0;
            *(float4*)&Bs[nbuf][br1][bc1] = pb1;
        }
        __syncthreads();
    }

    // epilogue: tanh(acc + bias), vectorized store
    float bia[8];
    #pragma unroll
    for (int j = 0; j < 8; j++) bia[j] = bk[col0 + tx * 8 + j];

    #pragma unroll
    for (int i = 0; i < 8; i++) {
        int r = row0 + ty * 8 + i;
        float4 o0, o1;
        o0.x = tanhf(acc[i][0] + bia[0]);
        o0.y = tanhf(acc[i][1] + bia[1]);
        o0.z = tanhf(acc[i][2] + bia[2]);
        o0.w = tanhf(acc[i][3] + bia[3]);
        o1.x = tanhf(acc[i][4] + bia[4]);
        o1.y = tanhf(acc[i][5] + bia[5]);
        o1.z = tanhf(acc[i][6] + bia[6]);
        o1.w = tanhf(acc[i][7] + bia[7]);
        float* op = &out[(size_t)r * N_DIM + col0 + tx * 8];
        *(float4*)op       = o0;
        *(float4*)(op + 4) = o1;
    }
}

// ---------------------------------------------------------------------------
// Kernel B: per-batch-row attention. 1 block (128 threads) per b.
// memory[b] (128x64 fp32 = 32KB) is staged through smem with COALESCED
// float4 loads (streaming hint), then each thread reads its own row from smem
// (row stride padded to 68 floats -> conflict-free LDS.128).
// ---------------------------------------------------------------------------
#define MEM_PITCH 68   // 64 + 4 pad floats; 272 B row stride (16B aligned)

__global__ __launch_bounds__(M_DIM)
void attn_kernel(const float* __restrict__ hidden,   // [B, 512]
                 const float* __restrict__ memory,   // [B, 128, 64]
                 const float* __restrict__ Wb,       // [512, 4]
                 const float* __restrict__ bb,       // [4]
                 const float* __restrict__ key,      // g_key [B, 256]
                 float* __restrict__ out)            // [B, 4, 128]
{
    __shared__ float mem_s[M_DIM][MEM_PITCH];        // ~34 KB
    __shared__ float key_s[N_DIM];
    __shared__ float u2_s[H_DIM];
    __shared__ float beta_s[H_DIM];
    __shared__ float red_max[H_DIM][4];
    __shared__ float red_sum[H_DIM][4];

    const int b    = blockIdx.x;
    const int tid  = threadIdx.x;
    const int lane = tid & 31;
    const int warp = tid >> 5;   // 0..3 == head id

    // ---- coalesced stage of memory[b] into smem ----
    {
        const float4* gp = (const float4*)&memory[(size_t)b * M_DIM * W_DIM];
        #pragma unroll
        for (int i = 0; i < 16; i++) {
            int f  = tid + i * M_DIM;        // 0..2047 float4 index
            int m  = f >> 4;                 // row
            int w4 = f & 15;                 // float4 within row
            float4 v = __ldcs(&gp[f]);
            *(float4*)&mem_s[m][w4 * 4] = v;
        }
    }

    // load key row into smem (256 floats, float2 each)
    {
        const float2* kp = (const float2*)&key[(size_t)b * N_DIM];
        *((float2*)key_s + tid) = kp[tid];
    }
    __syncthreads();

    // warp h: u2[h] = sum(key[h]^2) + EPS
    {
        float t0 = key_s[warp * W_DIM + lane];
        float t1 = key_s[warp * W_DIM + 32 + lane];
        float ss = t0 * t0 + t1 * t1;
        #pragma unroll
        for (int off = 16; off > 0; off >>= 1)
            ss += __shfl_xor_sync(0xffffffffu, ss, off);
        if (lane == 0) u2_s[warp] = ss + EPS;
    }

    // warp h: beta[h] = softplus(hidden[b] . Wb[:,h] + bb[h])
    {
        const float* hrow = &hidden[(size_t)b * D_DIM];
        float s = 0.f;
        #pragma unroll 4
        for (int d = lane; d < D_DIM; d += 32)
            s += hrow[d] * Wb[d * H_DIM + warp];
        #pragma unroll
        for (int off = 16; off > 0; off >>= 1)
            s += __shfl_xor_sync(0xffffffffu, s, off);
        if (lane == 0) {
            float x = s + bb[warp];
            beta_s[warp] = (x > 15.f) ? x : log1pf(expf(x));
        }
    }
    __syncthreads();

    // thread m: read own row from smem, accumulate v2 and 4 head dots
    const int m = tid;
    float v2 = 0.f;
    float num[H_DIM] = {0.f, 0.f, 0.f, 0.f};

    #pragma unroll
    for (int i = 0; i < W_DIM / 4; i++) {
        float4 v = *(const float4*)&mem_s[m][i * 4];
        v2 += v.x * v.x + v.y * v.y + v.z * v.z + v.w * v.w;
        #pragma unroll
        for (int h = 0; h < H_DIM; h++) {
            const float* ks = &key_s[h * W_DIM + i * 4];
            num[h] += ks[0] * v.x + ks[1] * v.y + ks[2] * v.z + ks[3] * v.w;
        }
    }
    v2 += EPS;

    // logits
    float l[H_DIM];
    #pragma unroll
    for (int h = 0; h < H_DIM; h++) {
        float den = sqrtf(u2_s[h] * v2);
        float k   = num[h] / (den + EPS);
        l[h] = k * beta_s[h];
    }

    // block softmax over the 128 threads, per head
    float mx[H_DIM];
    #pragma unroll
    for (int h = 0; h < H_DIM; h++) {
        float t = l[h];
        #pragma unroll
        for (int off = 16; off > 0; off >>= 1)
            t = fmaxf(t, __shfl_xor_sync(0xffffffffu, t, off));
        if (lane == 0) red_max[h][warp] = t;
    }
    __syncthreads();
    #pragma unroll
    for (int h = 0; h < H_DIM; h++)
        mx[h] = fmaxf(fmaxf(red_max[h][0], red_max[h][1]),
                      fmaxf(red_max[h][2], red_max[h][3]));

    float e[H_DIM], sm[H_DIM];
    #pragma unroll
    for (int h = 0; h < H_DIM; h++) {
        e[h] = __expf(l[h] - mx[h]);
        float t = e[h];
        #pragma unroll
        for (int off = 16; off > 0; off >>= 1)
            t += __shfl_xor_sync(0xffffffffu, t, off);
        if (lane == 0) red_sum[h][warp] = t;
    }
    __syncthreads();
    #pragma unroll
    for (int h = 0; h < H_DIM; h++)
        sm[h] = red_sum[h][0] + red_sum[h][1] + red_sum[h][2] + red_sum[h][3];

    // write wc[b,h,m]
    #pragma unroll
    for (int h = 0; h < H_DIM; h++)
        out[((size_t)b * H_DIM + h) * M_DIM + m] = e[h] / sm[h];
}

// ---------------------------------------------------------------------------
// Launch
// ---------------------------------------------------------------------------
extern "C" void kernel_launch(void* const* d_in, const int* in_sizes, int n_in,
                              void* d_out, int out_size)
{
    const float* hidden = (const float*)d_in[0];   // [8192, 512]
    const float* memory = (const float*)d_in[1];   // [8192, 128, 64]
    const float* W_key  = (const float*)d_in[2];   // [512, 256]
    const float* b_key  = (const float*)d_in[3];   // [256]
    const float* W_beta = (const float*)d_in[4];   // [512, 4]
    const float* b_beta = (const float*)d_in[5];   // [4]
    float* out = (float*)d_out;                    // [8192, 4, 128]

    float* keybuf;
    cudaGetSymbolAddress((void**)&keybuf, g_key);

    dim3 gridA(N_DIM / GBN, B_DIM / GBM);   // (2, 64) = 128 blocks
    key_gemm_kernel<<<gridA, 256>>>(hidden, W_key, b_key, keybuf);

    attn_kernel<<<B_DIM, M_DIM>>>(hidden, memory, W_beta, b_beta, keybuf, out);
}